// round 16
// baseline (speedup 1.0000x reference)
#include <cuda_runtime.h>
#include <cuda_bf16.h>
#include <cstdint>

#define NODES 50000
#define EDGES 800000
#define NB 196          // (NODES+255)/256
#define WPREP_N (256 * 256 + 128 * 256)
// IN=128, HID=256, LAT=64

// ============================ scratch ============================
__device__ int   g_cnt[NODES];       // zero-init at load; re-zeroed each replay in k_scan23
__device__ int   g_off[NODES + 1];
__device__ int   g_cur[NODES];
__device__ int   g_srcs[EDGES];
__device__ int   g_bsum[NB];
// tf32-prerounded fp32 operands
__device__ float g_ax[(size_t)NODES * 256];    // [meanx | x], rna-rounded to tf32
__device__ float g_h[(size_t)NODES * 256];     // h, rna-rounded to tf32
__device__ float g_w1t[256 * 256];             // [W1l;W1r]^T stored [n][k], rounded
__device__ float g_w2t[128 * 256];             // [W2l|W2r]^T stored [n][k], rounded
__device__ float g_q[(size_t)NODES * 64];
__device__ float g_r[(size_t)NODES * 64];

// ============================ TF32 MMA m16n8k8 ============================
#define MMATF32(d, a, b0, b1)                                                  \
    asm volatile(                                                              \
        "mma.sync.aligned.m16n8k8.row.col.f32.tf32.tf32.f32 "                  \
        "{%0,%1,%2,%3},{%4,%5,%6,%7},{%8,%9},{%0,%1,%2,%3};"                   \
        : "+f"((d)[0]), "+f"((d)[1]), "+f"((d)[2]), "+f"((d)[3])               \
        : "r"((a)[0]), "r"((a)[1]), "r"((a)[2]), "r"((a)[3]),                  \
          "r"(b0), "r"(b1))

__device__ __forceinline__ float tf32r(float x) {
    uint32_t u;
    asm("cvt.rna.tf32.f32 %0, %1;" : "=r"(u) : "f"(x));
    return __uint_as_float(u);
}

// ============================ cp.async ============================
__device__ __forceinline__ uint32_t smem_u32(const void* p) {
    uint32_t a;
    asm("{ .reg .u64 t; cvta.to.shared.u64 t, %1; cvt.u32.u64 %0, t; }" : "=r"(a) : "l"(p));
    return a;
}
__device__ __forceinline__ void cp16(uint32_t dst, const void* src, bool pred) {
    int sz = pred ? 16 : 0;   // src-size 0 -> zero-fill the 16B destination
    asm volatile("cp.async.cg.shared.global [%0], [%1], 16, %2;"
                 :: "r"(dst), "l"(src), "r"(sz));
}
#define CP_COMMIT() asm volatile("cp.async.commit_group;")
#define CP_WAIT(n)  asm volatile("cp.async.wait_group %0;" :: "n"(n))

// ============================ edge dtype detection ============================
__device__ __forceinline__ bool detect64(const int* ei32) {
    int o = 0;
    #pragma unroll
    for (int k = 1; k < 16; k += 2) o |= ei32[k];
    return o == 0;
}
__device__ __forceinline__ int load_idx(const void* ei, bool is64, int pos) {
    if (is64) return (int)((const long long*)ei)[pos];
    return ((const int*)ei)[pos];
}

// ============================ count + own-x round ============================
// count is atomic-bound — the x rounding rides along for free.
__global__ void __launch_bounds__(256) k_count(const void* __restrict__ ei,
                                               const float* __restrict__ x) {
    bool is64 = detect64((const int*)ei);
    int e = blockIdx.x * blockDim.x + threadIdx.x;
    if (e < EDGES) atomicAdd(&g_cnt[load_idx(ei, is64, EDGES + e)], 1);

    // own-x tf32 rounding -> cols 128..255 of g_ax (warp-per-row)
    const int lane = threadIdx.x & 31;
    int gw = blockIdx.x * 8 + (threadIdx.x >> 5);   // 3125 blocks * 8 warps
    for (int node = gw; node < NODES; node += 25000) {
        float4 xv = ((const float4*)(x + (size_t)node * 128))[lane];
        float4 o;
        o.x = tf32r(xv.x); o.y = tf32r(xv.y); o.z = tf32r(xv.z); o.w = tf32r(xv.w);
        ((float4*)(g_ax + (size_t)node * 256 + 128))[lane] = o;
    }
}

// ---- hierarchical scan ----
__device__ __forceinline__ int warp_incl_scan(int v, int lane) {
    int s = v;
    #pragma unroll
    for (int d = 1; d < 32; d <<= 1) {
        int t = __shfl_up_sync(0xFFFFFFFFu, s, d);
        if (lane >= d) s += t;
    }
    return s;
}

// scan1 + weight-prep (independent work folded in to save a launch)
__global__ void k_scan1(const float* __restrict__ W1l, const float* __restrict__ W1r,
                        const float* __restrict__ W2l, const float* __restrict__ W2r) {
    __shared__ int wsum[8];
    int t = threadIdx.x, lane = t & 31, wid = t >> 5;
    int i = blockIdx.x * 256 + t;
    int v = (i < NODES) ? g_cnt[i] : 0;
    int s = warp_incl_scan(v, lane);
    if (lane == 31) wsum[wid] = s;
    __syncthreads();
    if (wid == 0) {
        int ws = (lane < 8) ? wsum[lane] : 0;
        int sc = warp_incl_scan(ws, lane);
        if (lane < 8) wsum[lane] = sc - ws;
    }
    __syncthreads();
    int excl = (s - v) + wsum[wid];
    if (i < NODES) g_off[i] = excl;
    if (t == 255) g_bsum[blockIdx.x] = excl + v;

    // ---- weight transpose + tf32 round (grid-stride) ----
    for (int idx = i; idx < WPREP_N; idx += NB * 256) {
        if (idx < 256 * 256) {
            int n = idx & 255, k = idx >> 8;
            float w = (k < 128) ? W1l[k * 256 + n] : W1r[(k - 128) * 256 + n];
            g_w1t[n * 256 + k] = tf32r(w);
        } else {
            int j = idx - 256 * 256;
            int n = j >> 8, k = j & 255;
            float w = (n < 64) ? W2l[k * 64 + n] : W2r[k * 64 + (n - 64)];
            g_w2t[n * 256 + k] = tf32r(w);
        }
    }
}

// merged scan2+scan3: every block redundantly scans the 196 partials, applies
// its base; also re-zeroes g_cnt for the next graph replay.
__global__ void k_scan23() {
    __shared__ int wsum[8];
    __shared__ int sbase;
    int t = threadIdx.x, lane = t & 31, wid = t >> 5;
    int v = (t < NB) ? g_bsum[t] : 0;
    int s = warp_incl_scan(v, lane);
    if (lane == 31) wsum[wid] = s;
    __syncthreads();
    if (wid == 0) {
        int ws = (lane < 8) ? wsum[lane] : 0;
        int sc = warp_incl_scan(ws, lane);
        if (lane < 8) wsum[lane] = sc - ws;
    }
    __syncthreads();
    if (t == (int)blockIdx.x) sbase = (s - v) + wsum[wid];
    __syncthreads();
    int i = blockIdx.x * 256 + t;
    if (i < NODES) {
        int o = g_off[i] + sbase;
        g_off[i] = o;
        g_cur[i] = o;
        g_cnt[i] = 0;                  // ready for next replay
    }
    if (i == 0) g_off[NODES] = EDGES;
}

__global__ void k_scatter(const void* __restrict__ ei) {
    bool is64 = detect64((const int*)ei);
    int e = blockIdx.x * blockDim.x + threadIdx.x;
    if (e < EDGES) {
        int d = load_idx(ei, is64, EDGES + e);
        int s = load_idx(ei, is64, e);
        int p = atomicAdd(&g_cur[d], 1);
        g_srcs[p] = s;
    }
}

// ============================ layer-1 aggregation (gather+mean, tf32 round) ============================
__global__ void __launch_bounds__(256) k_agg1(const float* __restrict__ x) {
    const int node = blockIdx.x * 8 + (threadIdx.x >> 5);
    const int lane = threadIdx.x & 31;
    if (node >= NODES) return;
    const int s0 = g_off[node], s1 = g_off[node + 1];
    float4 acc = make_float4(0.f, 0.f, 0.f, 0.f);
    int j = s0;
    for (; j + 3 < s1; j += 4) {
        int sa = g_srcs[j], sb = g_srcs[j + 1], sc = g_srcs[j + 2], sd = g_srcs[j + 3];
        float4 va = ((const float4*)(x + (size_t)sa * 128))[lane];
        float4 vb = ((const float4*)(x + (size_t)sb * 128))[lane];
        float4 vc = ((const float4*)(x + (size_t)sc * 128))[lane];
        float4 vd = ((const float4*)(x + (size_t)sd * 128))[lane];
        acc.x += (va.x + vb.x) + (vc.x + vd.x);
        acc.y += (va.y + vb.y) + (vc.y + vd.y);
        acc.z += (va.z + vb.z) + (vc.z + vd.z);
        acc.w += (va.w + vb.w) + (vc.w + vd.w);
    }
    for (; j < s1; j++) {
        int sa = g_srcs[j];
        float4 va = ((const float4*)(x + (size_t)sa * 128))[lane];
        acc.x += va.x; acc.y += va.y; acc.z += va.z; acc.w += va.w;
    }
    int deg = s1 - s0;
    float inv = 1.0f / (float)(deg > 0 ? deg : 1);
    float4 o;
    o.x = tf32r(acc.x * inv); o.y = tf32r(acc.y * inv);
    o.z = tf32r(acc.z * inv); o.w = tf32r(acc.w * inv);
    ((float4*)(g_ax + (size_t)node * 256))[lane] = o;
}

// ============================ fused TF32 GEMM (layer1 + layer2) ============================
// Grid: 391 row tiles. Per CTA:
//   Phase A/B (hc=0,1): h[:,hc*128:+128] = relu(g_ax @ W1[:,half] + b1) -> g_h (rounded)
//   Phase C: [q|r] = h_tile @ [W2l|W2r] (+b2), rows re-read L2-hot
// 2-stage cp.async pipeline, K=32 chunks, ONE sync per chunk (R15 structure).
// Stage: A tile 128 rows x 32 fp32 + B tile same, row stride 36 words (pad 4):
// staging STS.128 and frag LDS both map to (4r+fc) mod 32 -> conflict-free.
#define ROWW 36
#define OB   (128 * ROWW)            // B tile offset in words
#define BUFW (2 * 128 * ROWW)        // 9216 words per buffer
#define GEMM_SMEM (2 * BUFW * 4)     // 72 KB -> 2 CTAs/SM

__device__ __forceinline__ void gemm_fill(uint32_t sbase, int buf,
                                          const float* A, const float* B,
                                          size_t ao, size_t bo, bool valid,
                                          int srow, int shw) {
    uint32_t d = sbase + (buf * BUFW + srow * ROWW + shw) * 4;
    cp16(d,      A + ao,      valid);
    cp16(d + 16, A + ao + 4,  valid);
    cp16(d + 32, A + ao + 8,  valid);
    cp16(d + 48, A + ao + 12, valid);
    uint32_t db = d + OB * 4;
    cp16(db,      B + bo,      true);
    cp16(db + 16, B + bo + 4,  true);
    cp16(db + 32, B + bo + 8,  true);
    cp16(db + 48, B + bo + 12, true);
}

// TF32 MMA over one buffer: 4 k=8 substeps.
// A frag: a0..a3 = (fr,fc),(fr+8,fc),(fr,fc+4),(fr+8,fc+4)
// B frag [n][k]: b0,b1 = [n0+fr][fc],[n0+fr][fc+4]
#define GEMM_MMA_CHUNK(bufv)                                                   \
    {                                                                          \
        const uint32_t* sA = smw + (bufv) * BUFW;                              \
        const uint32_t* sB = sA + OB;                                          \
        _Pragma("unroll")                                                      \
        for (int s = 0; s < 4; s++) {                                          \
            uint32_t a[2][4];                                                  \
            _Pragma("unroll")                                                  \
            for (int i = 0; i < 2; i++) {                                      \
                int R = wr * 32 + i * 16;                                      \
                a[i][0] = sA[(R + fr) * ROWW + s * 8 + fc];                    \
                a[i][1] = sA[(R + fr + 8) * ROWW + s * 8 + fc];                \
                a[i][2] = sA[(R + fr) * ROWW + s * 8 + fc + 4];                \
                a[i][3] = sA[(R + fr + 8) * ROWW + s * 8 + fc + 4];            \
            }                                                                  \
            _Pragma("unroll")                                                  \
            for (int j = 0; j < 8; j++) {                                      \
                int n = wc * 64 + j * 8 + fr;                                  \
                uint32_t b0 = sB[n * ROWW + s * 8 + fc];                       \
                uint32_t b1 = sB[n * ROWW + s * 8 + fc + 4];                   \
                _Pragma("unroll")                                              \
                for (int i = 0; i < 2; i++)                                    \
                    MMATF32(acc[i][j], a[i], b0, b1);                          \
            }                                                                  \
        }                                                                      \
    }

// one sync per chunk: wait(0) publishes chunk c; the same sync proves MMA(c-1)
// retired (it read the buffer being refilled) so the refill is safe.
#define GEMM_PHASE(Ap, Bp, aRowG, bRowG)                                       \
    gemm_fill(sbase, 0, Ap, Bp,                                                \
              (size_t)(aRowG) * 256 + shw, (size_t)(bRowG) * 256 + shw,        \
              valid, srow, shw);                                               \
    CP_COMMIT();                                                               \
    _Pragma("unroll 1")                                                        \
    for (int c = 0; c < 8; c++) {                                              \
        CP_WAIT(0);                                                            \
        __syncthreads();                                                       \
        if (c < 7) {                                                           \
            gemm_fill(sbase, (c + 1) & 1, Ap, Bp,                              \
                      (size_t)(aRowG) * 256 + (c + 1) * 32 + shw,              \
                      (size_t)(bRowG) * 256 + (c + 1) * 32 + shw,              \
                      valid, srow, shw);                                       \
            CP_COMMIT();                                                       \
        }                                                                      \
        GEMM_MMA_CHUNK(c & 1);                                                 \
    }

__global__ void __launch_bounds__(256, 2) k_gemm(const float* __restrict__ b1,
                                                 const float* __restrict__ b2) {
    extern __shared__ uint32_t smw[];
    __shared__ float sb1[256];
    __shared__ float sb2[64];
    const int tid = threadIdx.x, lane = tid & 31, w = tid >> 5;
    const int wr = w >> 1, wc = w & 1;         // warp grid 4x2, warp tile 32x64
    const int row0 = blockIdx.x * 128;
    sb1[tid] = b1[tid];
    if (tid < 64) sb2[tid] = b2[tid];

    const int srow = tid >> 1;                 // staging row 0..127
    const int shw  = (tid & 1) * 16;           // word offset 0 or 16
    const int grow = row0 + srow;
    const bool valid = grow < NODES;
    const int fr = lane >> 2, fc = lane & 3;
    const uint32_t sbase = smem_u32(smw);

    float acc[2][8][4];

    // ---- phases A/B: h column halves ----
    #pragma unroll 1
    for (int hc = 0; hc < 2; hc++) {
        #pragma unroll
        for (int i = 0; i < 2; i++)
            #pragma unroll
            for (int jj = 0; jj < 8; jj++)
                #pragma unroll
                for (int kk = 0; kk < 4; kk++) acc[i][jj][kk] = 0.f;

        const float* Ap = g_ax;
        const float* Bp = g_w1t;
        const int brow = hc * 128 + srow;

        GEMM_PHASE(Ap, Bp, grow, brow);

        // epilogue: +bias, relu, tf32 round -> g_h (cols hc*128..+127)
        #pragma unroll
        for (int i = 0; i < 2; i++) {
            #pragma unroll
            for (int j = 0; j < 8; j++) {
                int r1 = row0 + wr * 32 + i * 16 + fr;
                int cl = wc * 64 + j * 8 + fc * 2;         // 0..127 within half
                float bb0 = sb1[hc * 128 + cl], bb1 = sb1[hc * 128 + cl + 1];
                #pragma unroll
                for (int hh = 0; hh < 2; hh++) {
                    int rr = r1 + hh * 8;
                    if (rr < NODES) {
                        float2 o;
                        o.x = tf32r(fmaxf(acc[i][j][hh * 2 + 0] + bb0, 0.f));
                        o.y = tf32r(fmaxf(acc[i][j][hh * 2 + 1] + bb1, 0.f));
                        *(float2*)&g_h[(size_t)rr * 256 + hc * 128 + cl] = o;
                    }
                }
            }
        }
        __syncthreads();   // publish this half's global stores block-wide
    }

    // ---- phase C: [q|r] = h_tile @ W2 (rows L2-hot from phases A/B) ----
    #pragma unroll
    for (int i = 0; i < 2; i++)
        #pragma unroll
        for (int jj = 0; jj < 8; jj++)
            #pragma unroll
            for (int kk = 0; kk < 4; kk++) acc[i][jj][kk] = 0.f;

    {
        const float* Ap = g_h;
        const float* Bp = g_w2t;
        GEMM_PHASE(Ap, Bp, grow, srow);
    }

    // epilogue: wc==0 -> q (no bias), wc==1 -> r (+b2)
    #pragma unroll
    for (int i = 0; i < 2; i++) {
        #pragma unroll
        for (int j = 0; j < 8; j++) {
            int r1 = row0 + wr * 32 + i * 16 + fr;
            int cc = j * 8 + fc * 2;
            #pragma unroll
            for (int hh = 0; hh < 2; hh++) {
                int rr = r1 + hh * 8;
                if (rr < NODES) {
                    float2 v;
                    v.x = acc[i][j][hh * 2 + 0];
                    v.y = acc[i][j][hh * 2 + 1];
                    if (wc == 0) {
                        *(float2*)&g_q[(size_t)rr * 64 + cc] = v;
                    } else {
                        v.x += sb2[cc];
                        v.y += sb2[cc + 1];
                        *(float2*)&g_r[(size_t)rr * 64 + cc] = v;
                    }
                }
            }
        }
    }
}

// ============================ layer-2 aggregation + z + fused decoder ============================
__global__ void __launch_bounds__(256) k_agg2(const float* __restrict__ Wd,
                                              const float* __restrict__ bd,
                                              float* __restrict__ z_out,
                                              float* __restrict__ xh_out) {
    __shared__ float4 sWd[64 * 32];
    __shared__ float  sZ[8][64];
    for (int i = threadIdx.x; i < 64 * 32; i += blockDim.x)
        sWd[i] = ((const float4*)Wd)[i];
    __syncthreads();

    const int wid = threadIdx.x >> 5;
    const int lane = threadIdx.x & 31;
    const int node = blockIdx.x * 8 + wid;
    if (node < NODES) {
        const int s0 = g_off[node], s1 = g_off[node + 1];
        float2 acc = make_float2(0.f, 0.f);
        int j = s0;
        for (; j + 3 < s1; j += 4) {
            int sa = g_srcs[j], sb = g_srcs[j + 1], sc = g_srcs[j + 2], sd = g_srcs[j + 3];
            float2 va = ((const float2*)(g_q + (size_t)sa * 64))[lane];
            float2 vb = ((const float2*)(g_q + (size_t)sb * 64))[lane];
            float2 vc = ((const float2*)(g_q + (size_t)sc * 64))[lane];
            float2 vd = ((const float2*)(g_q + (size_t)sd * 64))[lane];
            acc.x += (va.x + vb.x) + (vc.x + vd.x);
            acc.y += (va.y + vb.y) + (vc.y + vd.y);
        }
        for (; j < s1; j++) {
            int sa = g_srcs[j];
            float2 va = ((const float2*)(g_q + (size_t)sa * 64))[lane];
            acc.x += va.x; acc.y += va.y;
        }
        int deg = s1 - s0;
        float inv = 1.0f / (float)(deg > 0 ? deg : 1);
        float2 r2 = ((const float2*)(g_r + (size_t)node * 64))[lane];
        float2 zv;
        zv.x = acc.x * inv + r2.x;
        zv.y = acc.y * inv + r2.y;
        ((float2*)(z_out + (size_t)node * 64))[lane] = zv;
        sZ[wid][lane * 2]     = zv.x;
        sZ[wid][lane * 2 + 1] = zv.y;
        __syncwarp();
        float4 o = ((const float4*)bd)[lane];
        #pragma unroll 8
        for (int k = 0; k < 64; k++) {
            float zk = sZ[wid][k];
            float4 wv = sWd[k * 32 + lane];
            o.x = fmaf(zk, wv.x, o.x);
            o.y = fmaf(zk, wv.y, o.y);
            o.z = fmaf(zk, wv.z, o.z);
            o.w = fmaf(zk, wv.w, o.w);
        }
        ((float4*)(xh_out + (size_t)node * 128))[lane] = o;
    }
}

// ============================ launcher ============================
extern "C" void kernel_launch(void* const* d_in, const int* in_sizes, int n_in,
                              void* d_out, int out_size) {
    const float* x   = (const float*)d_in[0];
    const void*  ei  = d_in[1];
    const float* W1l = (const float*)d_in[2];
    const float* b1  = (const float*)d_in[3];
    const float* W1r = (const float*)d_in[4];
    const float* W2l = (const float*)d_in[5];
    const float* b2  = (const float*)d_in[6];
    const float* W2r = (const float*)d_in[7];
    const float* Wd  = (const float*)d_in[8];
    const float* bd  = (const float*)d_in[9];

    float* z_out  = (float*)d_out;                       // [N,64]
    float* xh_out = (float*)d_out + (size_t)NODES * 64;  // [N,128]

    cudaFuncSetAttribute(k_gemm, cudaFuncAttributeMaxDynamicSharedMemorySize, GEMM_SMEM);

    const int MT = (NODES + 127) / 128;   // 391 row tiles

    k_count<<<(EDGES + 255) / 256, 256>>>(ei, x);
    k_scan1<<<NB, 256>>>(W1l, W1r, W2l, W2r);
    k_scan23<<<NB, 256>>>();
    k_scatter<<<(EDGES + 255) / 256, 256>>>(ei);
    k_agg1<<<(NODES + 7) / 8, 256>>>(x);
    k_gemm<<<MT, 256, GEMM_SMEM>>>(b1, b2);
    k_agg2<<<(NODES + 7) / 8, 256>>>(Wd, bd, z_out, xh_out);
}

// round 17
// speedup vs baseline: 1.4442x; 1.4442x over previous
#include <cuda_runtime.h>
#include <cuda_bf16.h>
#include <cstdint>

#define NODES 50000
#define EDGES 800000
#define NB 196          // (NODES+255)/256
#define WPREP_N (256 * 256 + 128 * 256)
// IN=128, HID=256, LAT=64

// ============================ scratch ============================
__device__ int   g_cnt[NODES];       // zero-init at load; re-zeroed each replay in k_scan23
__device__ int   g_off[NODES + 1];
__device__ int   g_cur[NODES];
__device__ int   g_srcs[EDGES];
__device__ int   g_bsum[NB];
// bf16 split operands
__device__ __nv_bfloat16 g_axh[(size_t)NODES * 256];   // [meanx_hi | x_hi]
__device__ __nv_bfloat16 g_axl[(size_t)NODES * 256];   // [meanx_lo | x_lo]
__device__ __nv_bfloat16 g_hh[(size_t)NODES * 256];    // h hi
__device__ __nv_bfloat16 g_hl[(size_t)NODES * 256];    // h lo
__device__ __nv_bfloat16 g_w1t_hi[256 * 256];          // B1 = [W1l;W1r]^T stored [n][k]
__device__ __nv_bfloat16 g_w1t_lo[256 * 256];
__device__ __nv_bfloat16 g_w2t_hi[128 * 256];          // B2 = [W2l|W2r]^T stored [n][k]
__device__ __nv_bfloat16 g_w2t_lo[128 * 256];
__device__ float g_q[(size_t)NODES * 64];
__device__ float g_r[(size_t)NODES * 64];

// ============================ HMMA m16n8k16 bf16 + ldmatrix ============================
#define MMA16816(d, a, b0, b1)                                                 \
    asm volatile(                                                              \
        "mma.sync.aligned.m16n8k16.row.col.f32.bf16.bf16.f32 "                 \
        "{%0,%1,%2,%3},{%4,%5,%6,%7},{%8,%9},{%0,%1,%2,%3};"                   \
        : "+f"((d)[0]), "+f"((d)[1]), "+f"((d)[2]), "+f"((d)[3])               \
        : "r"((a)[0]), "r"((a)[1]), "r"((a)[2]), "r"((a)[3]),                  \
          "r"(b0), "r"(b1))

#define LDSM4(r, addr)                                                         \
    asm volatile("ldmatrix.sync.aligned.m8n8.x4.shared.b16 {%0,%1,%2,%3}, [%4];" \
        : "=r"((r)[0]), "=r"((r)[1]), "=r"((r)[2]), "=r"((r)[3]) : "r"(addr))

// ============================ cp.async ============================
__device__ __forceinline__ uint32_t smem_u32(const void* p) {
    uint32_t a;
    asm("{ .reg .u64 t; cvta.to.shared.u64 t, %1; cvt.u32.u64 %0, t; }" : "=r"(a) : "l"(p));
    return a;
}
__device__ __forceinline__ void cp16(uint32_t dst, const void* src, bool pred) {
    int sz = pred ? 16 : 0;   // src-size 0 -> zero-fill the 16B destination
    asm volatile("cp.async.cg.shared.global [%0], [%1], 16, %2;"
                 :: "r"(dst), "l"(src), "r"(sz));
}
#define CP_COMMIT() asm volatile("cp.async.commit_group;")
#define CP_WAIT(n)  asm volatile("cp.async.wait_group %0;" :: "n"(n))

// ============================ edge dtype detection ============================
__device__ __forceinline__ bool detect64(const int* ei32) {
    int o = 0;
    #pragma unroll
    for (int k = 1; k < 16; k += 2) o |= ei32[k];
    return o == 0;
}
__device__ __forceinline__ int load_idx(const void* ei, bool is64, int pos) {
    if (is64) return (int)((const long long*)ei)[pos];
    return ((const int*)ei)[pos];
}

// ============================ bf16 split helper ============================
__device__ __forceinline__ void split_store4(__nv_bfloat16* hi_base, __nv_bfloat16* lo_base,
                                             float4 v) {
    __nv_bfloat16 h0 = __float2bfloat16(v.x), h1 = __float2bfloat16(v.y);
    __nv_bfloat16 h2 = __float2bfloat16(v.z), h3 = __float2bfloat16(v.w);
    __nv_bfloat162 a, b;
    a.x = h0; a.y = h1; b.x = h2; b.y = h3;
    *(__nv_bfloat162*)(hi_base) = a;
    *(__nv_bfloat162*)(hi_base + 2) = b;
    __nv_bfloat162 la, lb;
    la.x = __float2bfloat16(v.x - __bfloat162float(h0));
    la.y = __float2bfloat16(v.y - __bfloat162float(h1));
    lb.x = __float2bfloat16(v.z - __bfloat162float(h2));
    lb.y = __float2bfloat16(v.w - __bfloat162float(h3));
    *(__nv_bfloat162*)(lo_base) = la;
    *(__nv_bfloat162*)(lo_base + 2) = lb;
}

// ============================ count + own-x split ============================
// count is atomic-bound (issue ~6%) — the x split rides along for free.
__global__ void __launch_bounds__(256) k_count(const void* __restrict__ ei,
                                               const float* __restrict__ x) {
    bool is64 = detect64((const int*)ei);
    int e = blockIdx.x * blockDim.x + threadIdx.x;
    if (e < EDGES) atomicAdd(&g_cnt[load_idx(ei, is64, EDGES + e)], 1);

    // own-x bf16 split -> cols 128..255 of g_axh/g_axl (warp-per-row)
    const int lane = threadIdx.x & 31;
    int gw = blockIdx.x * 8 + (threadIdx.x >> 5);   // 0..24999 (3125 blocks)
    for (int node = gw; node < NODES; node += 25000) {
        float4 xv = ((const float4*)(x + (size_t)node * 128))[lane];
        size_t base = (size_t)node * 256 + 128 + lane * 4;
        split_store4(g_axh + base, g_axl + base, xv);
    }
}

// ---- hierarchical scan ----
__device__ __forceinline__ int warp_incl_scan(int v, int lane) {
    int s = v;
    #pragma unroll
    for (int d = 1; d < 32; d <<= 1) {
        int t = __shfl_up_sync(0xFFFFFFFFu, s, d);
        if (lane >= d) s += t;
    }
    return s;
}

// scan1 + weight-prep (independent work folded in to save a launch)
__global__ void k_scan1(const float* __restrict__ W1l, const float* __restrict__ W1r,
                        const float* __restrict__ W2l, const float* __restrict__ W2r) {
    __shared__ int wsum[8];
    int t = threadIdx.x, lane = t & 31, wid = t >> 5;
    int i = blockIdx.x * 256 + t;
    int v = (i < NODES) ? g_cnt[i] : 0;
    int s = warp_incl_scan(v, lane);
    if (lane == 31) wsum[wid] = s;
    __syncthreads();
    if (wid == 0) {
        int ws = (lane < 8) ? wsum[lane] : 0;
        int sc = warp_incl_scan(ws, lane);
        if (lane < 8) wsum[lane] = sc - ws;
    }
    __syncthreads();
    int excl = (s - v) + wsum[wid];
    if (i < NODES) g_off[i] = excl;
    if (t == 255) g_bsum[blockIdx.x] = excl + v;

    // ---- weight transpose + bf16 split (grid-stride) ----
    for (int idx = i; idx < WPREP_N; idx += NB * 256) {
        if (idx < 256 * 256) {
            int n = idx & 255, k = idx >> 8;
            float w = (k < 128) ? W1l[k * 256 + n] : W1r[(k - 128) * 256 + n];
            __nv_bfloat16 hi = __float2bfloat16(w);
            g_w1t_hi[n * 256 + k] = hi;
            g_w1t_lo[n * 256 + k] = __float2bfloat16(w - __bfloat162float(hi));
        } else {
            int j = idx - 256 * 256;
            int n = j >> 8, k = j & 255;
            float w = (n < 64) ? W2l[k * 64 + n] : W2r[k * 64 + (n - 64)];
            __nv_bfloat16 hi = __float2bfloat16(w);
            g_w2t_hi[n * 256 + k] = hi;
            g_w2t_lo[n * 256 + k] = __float2bfloat16(w - __bfloat162float(hi));
        }
    }
}

// merged scan2+scan3: every block redundantly scans the 196 partials, applies
// its base; also re-zeroes g_cnt for the next graph replay.
__global__ void k_scan23() {
    __shared__ int wsum[8];
    __shared__ int sbase;
    int t = threadIdx.x, lane = t & 31, wid = t >> 5;
    int v = (t < NB) ? g_bsum[t] : 0;
    int s = warp_incl_scan(v, lane);
    if (lane == 31) wsum[wid] = s;
    __syncthreads();
    if (wid == 0) {
        int ws = (lane < 8) ? wsum[lane] : 0;
        int sc = warp_incl_scan(ws, lane);
        if (lane < 8) wsum[lane] = sc - ws;
    }
    __syncthreads();
    if (t == (int)blockIdx.x) sbase = (s - v) + wsum[wid];
    __syncthreads();
    int i = blockIdx.x * 256 + t;
    if (i < NODES) {
        int o = g_off[i] + sbase;
        g_off[i] = o;
        g_cur[i] = o;
        g_cnt[i] = 0;                  // ready for next replay
    }
    if (i == 0) g_off[NODES] = EDGES;
}

__global__ void k_scatter(const void* __restrict__ ei) {
    bool is64 = detect64((const int*)ei);
    int e = blockIdx.x * blockDim.x + threadIdx.x;
    if (e < EDGES) {
        int d = load_idx(ei, is64, EDGES + e);
        int s = load_idx(ei, is64, e);
        int p = atomicAdd(&g_cur[d], 1);
        g_srcs[p] = s;
    }
}

// ============================ layer-1 aggregation ============================
// Gathers the bf16(x) copy (cols 128..255 of g_axh, written by k_count):
// halves the dominant L2 gather traffic (205MB vs 410MB). Accumulate fp32.
__global__ void __launch_bounds__(256) k_agg1() {
    const int node = blockIdx.x * 8 + (threadIdx.x >> 5);
    const int lane = threadIdx.x & 31;
    if (node >= NODES) return;
    const int s0 = g_off[node], s1 = g_off[node + 1];
    float4 acc = make_float4(0.f, 0.f, 0.f, 0.f);
    const __nv_bfloat16* xb = g_axh + 128 + lane * 4;   // row base + own offset
    int j = s0;
    for (; j + 3 < s1; j += 4) {
        int sa = g_srcs[j], sb = g_srcs[j + 1], sc = g_srcs[j + 2], sd = g_srcs[j + 3];
        uint2 ua = *(const uint2*)(xb + (size_t)sa * 256);
        uint2 ub = *(const uint2*)(xb + (size_t)sb * 256);
        uint2 uc = *(const uint2*)(xb + (size_t)sc * 256);
        uint2 ud = *(const uint2*)(xb + (size_t)sd * 256);
        float2 a0 = __bfloat1622float2(*(__nv_bfloat162*)&ua.x);
        float2 a1 = __bfloat1622float2(*(__nv_bfloat162*)&ua.y);
        float2 b0 = __bfloat1622float2(*(__nv_bfloat162*)&ub.x);
        float2 b1 = __bfloat1622float2(*(__nv_bfloat162*)&ub.y);
        float2 c0 = __bfloat1622float2(*(__nv_bfloat162*)&uc.x);
        float2 c1 = __bfloat1622float2(*(__nv_bfloat162*)&uc.y);
        float2 d0 = __bfloat1622float2(*(__nv_bfloat162*)&ud.x);
        float2 d1 = __bfloat1622float2(*(__nv_bfloat162*)&ud.y);
        acc.x += (a0.x + b0.x) + (c0.x + d0.x);
        acc.y += (a0.y + b0.y) + (c0.y + d0.y);
        acc.z += (a1.x + b1.x) + (c1.x + d1.x);
        acc.w += (a1.y + b1.y) + (c1.y + d1.y);
    }
    for (; j < s1; j++) {
        int sa = g_srcs[j];
        uint2 ua = *(const uint2*)(xb + (size_t)sa * 256);
        float2 a0 = __bfloat1622float2(*(__nv_bfloat162*)&ua.x);
        float2 a1 = __bfloat1622float2(*(__nv_bfloat162*)&ua.y);
        acc.x += a0.x; acc.y += a0.y; acc.z += a1.x; acc.w += a1.y;
    }
    int deg = s1 - s0;
    float inv = 1.0f / (float)(deg > 0 ? deg : 1);
    acc.x *= inv; acc.y *= inv; acc.z *= inv; acc.w *= inv;
    size_t base = (size_t)node * 256 + lane * 4;
    split_store4(g_axh + base, g_axl + base, acc);
}

// ============================ fused HMMA GEMM (layer1 + layer2) ============================
// Grid: 391 row tiles. Per CTA:
//   Phase A/B (hc=0,1): h[:,hc*128:+128] = relu([meanx|x] @ W1[:,half] + b1)  -> g_hh/g_hl
//   Phase C: [q|r] = h_tile @ [W2l|W2r] (+b2), rows re-read L2-hot
// 2-stage cp.async pipeline, K=32 chunks (16 pairs), ONE sync per chunk:
//   wait(0) -> sync -> fill(c+1) -> MMA(c)
// Buffer layout: 2 buffers x (Ah|Al|Bh|Bl), 128 rows x 16 pairs at stride 20
// words (conflict-free staging stores + LDSM loads).
#define BUFW 10240
#define OAH 0
#define OAL 2560
#define OBH 5120
#define OBL 7680
#define GEMM_SMEM (2 * BUFW * 4)     // 80 KB -> 2 CTAs/SM

__device__ __forceinline__ void gemm_fill(uint32_t sbase, int buf,
                                          const uint32_t* aH, const uint32_t* aL,
                                          const uint32_t* bH, const uint32_t* bL,
                                          size_t ao, size_t bo, bool valid,
                                          int srow, int soff) {
    uint32_t d = sbase + (buf * BUFW + srow * 20 + soff) * 4;
    cp16(d + OAH * 4,      aH + ao,     valid);
    cp16(d + OAH * 4 + 16, aH + ao + 4, valid);
    cp16(d + OAL * 4,      aL + ao,     valid);
    cp16(d + OAL * 4 + 16, aL + ao + 4, valid);
    cp16(d + OBH * 4,      bH + bo,     true);
    cp16(d + OBH * 4 + 16, bH + bo + 4, true);
    cp16(d + OBL * 4,      bL + bo,     true);
    cp16(d + OBL * 4 + 16, bL + bo + 4, true);
}

// ldmatrix-based MMA over one buffer (K=32: two K=16 sub-steps).
// A frag x4: lane -> row (lane&7)+((lane>>3)&1)*8, k-half (lane>>4) -> {a0..a3}
// B frag x4: lane -> n (lane>>4)*8+(lane&7),  k-half ((lane>>3)&1) -> {b0,b1} x2
#define GEMM_MMA_CHUNK(bufv)                                                   \
    {                                                                          \
        const uint32_t bb = sbase + (bufv) * (BUFW * 4);                       \
        _Pragma("unroll")                                                      \
        for (int s = 0; s < 2; s++) {                                          \
            uint32_t ah[2][4], al[2][4];                                       \
            _Pragma("unroll")                                                  \
            for (int i = 0; i < 2; i++) {                                      \
                uint32_t aaddr = bb +                                          \
                    (OAH + (wr * 32 + i * 16 + aRow) * 20 + s * 8 + aKh) * 4;  \
                LDSM4(ah[i], aaddr);                                           \
                LDSM4(al[i], aaddr + (OAL - OAH) * 4);                         \
            }                                                                  \
            _Pragma("unroll")                                                  \
            for (int jh = 0; jh < 2; jh++) {                                   \
                uint32_t bh[2][4], bl[2][4];                                   \
                _Pragma("unroll")                                              \
                for (int q = 0; q < 2; q++) {                                  \
                    uint32_t baddr = bb +                                      \
                        (OBH + (wc * 64 + (jh * 2 + q) * 16 + bRow) * 20       \
                         + s * 8 + bKh) * 4;                                   \
                    LDSM4(bh[q], baddr);                                       \
                    LDSM4(bl[q], baddr + (OBL - OBH) * 4);                     \
                }                                                              \
                _Pragma("unroll")                                              \
                for (int q = 0; q < 2; q++) {                                  \
                    _Pragma("unroll")                                          \
                    for (int p = 0; p < 2; p++) {                              \
                        int j = jh * 4 + q * 2 + p;                            \
                        uint32_t b0 = bh[q][p * 2], b1v = bh[q][p * 2 + 1];    \
                        uint32_t c0 = bl[q][p * 2], c1v = bl[q][p * 2 + 1];    \
                        _Pragma("unroll")                                      \
                        for (int i = 0; i < 2; i++) {                          \
                            MMA16816(acc[i][j], ah[i], b0, b1v);               \
                            MMA16816(acc[i][j], ah[i], c0, c1v);               \
                            MMA16816(acc[i][j], al[i], b0, b1v);               \
                        }                                                      \
                    }                                                          \
                }                                                              \
            }                                                                  \
        }                                                                      \
    }

// one sync per chunk: wait(0) publishes chunk c; the same sync proves MMA(c-1)
// retired (it read the buffer being refilled) so the refill below is safe.
#define GEMM_PHASE(aH, aL, bH, bL, aRowG, bRowG)                               \
    gemm_fill(sbase, 0, aH, aL, bH, bL,                                        \
              (size_t)(aRowG) * 128 + soff, (size_t)(bRowG) * 128 + soff,      \
              valid, srow, soff);                                              \
    CP_COMMIT();                                                               \
    _Pragma("unroll 1")                                                        \
    for (int c = 0; c < 8; c++) {                                              \
        CP_WAIT(0);                                                            \
        __syncthreads();                                                       \
        if (c < 7) {                                                           \
            gemm_fill(sbase, (c + 1) & 1, aH, aL, bH, bL,                      \
                      (size_t)(aRowG) * 128 + (c + 1) * 16 + soff,             \
                      (size_t)(bRowG) * 128 + (c + 1) * 16 + soff,             \
                      valid, srow, soff);                                      \
            CP_COMMIT();                                                       \
        }                                                                      \
        GEMM_MMA_CHUNK(c & 1);                                                 \
    }

__global__ void __launch_bounds__(256, 2) k_gemm(const float* __restrict__ b1,
                                                 const float* __restrict__ b2) {
    extern __shared__ uint32_t smw[];
    __shared__ float sb1[256];
    __shared__ float sb2[64];
    const int tid = threadIdx.x, lane = tid & 31, w = tid >> 5;
    const int wr = w >> 1, wc = w & 1;         // warp grid 4x2, warp tile 32x64
    const int row0 = blockIdx.x * 128;
    sb1[tid] = b1[tid];
    if (tid < 64) sb2[tid] = b2[tid];

    const int srow = tid >> 1;                 // staging row 0..127
    const int soff = (tid & 1) * 8;            // word offset 0 or 8 (2x16B)
    const int grow = row0 + srow;
    const bool valid = grow < NODES;
    const int fr = lane >> 2, fc = lane & 3;
    // ldmatrix lane-address components
    const int aRow = (lane & 7) + ((lane >> 3) & 1) * 8;  // row within 16
    const int aKh  = (lane >> 4) * 4;                     // k-half word offset
    const int bRow = (lane >> 4) * 8 + (lane & 7);        // n within 16
    const int bKh  = ((lane >> 3) & 1) * 4;
    const uint32_t sbase = smem_u32(smw);

    float acc[2][8][4];

    // ---- phases A/B: h column halves ----
    #pragma unroll 1
    for (int hc = 0; hc < 2; hc++) {
        #pragma unroll
        for (int i = 0; i < 2; i++)
            #pragma unroll
            for (int jj = 0; jj < 8; jj++)
                #pragma unroll
                for (int kk = 0; kk < 4; kk++) acc[i][jj][kk] = 0.f;

        const uint32_t* aH = (const uint32_t*)g_axh;
        const uint32_t* aL = (const uint32_t*)g_axl;
        const uint32_t* bH = (const uint32_t*)g_w1t_hi;
        const uint32_t* bL = (const uint32_t*)g_w1t_lo;
        const int brow = hc * 128 + srow;

        GEMM_PHASE(aH, aL, bH, bL, grow, brow);

        // epilogue: +bias, relu, bf16 split -> g_hh/g_hl (cols hc*128..+127)
        #pragma unroll
        for (int i = 0; i < 2; i++) {
            #pragma unroll
            for (int j = 0; j < 8; j++) {
                int r1 = row0 + wr * 32 + i * 16 + fr;
                int cl = wc * 64 + j * 8 + fc * 2;         // 0..127 within half
                float bb0 = sb1[hc * 128 + cl], bb1 = sb1[hc * 128 + cl + 1];
                #pragma unroll
                for (int hh = 0; hh < 2; hh++) {
                    int rr = r1 + hh * 8;
                    if (rr < NODES) {
                        float v0 = fmaxf(acc[i][j][hh * 2 + 0] + bb0, 0.f);
                        float v1 = fmaxf(acc[i][j][hh * 2 + 1] + bb1, 0.f);
                        __nv_bfloat16 h0 = __float2bfloat16(v0);
                        __nv_bfloat16 h1 = __float2bfloat16(v1);
                        __nv_bfloat162 ph; ph.x = h0; ph.y = h1;
                        __nv_bfloat162 pl;
                        pl.x = __float2bfloat16(v0 - __bfloat162float(h0));
                        pl.y = __float2bfloat16(v1 - __bfloat162float(h1));
                        size_t o = (size_t)rr * 256 + hc * 128 + cl;
                        *(__nv_bfloat162*)(g_hh + o) = ph;
                        *(__nv_bfloat162*)(g_hl + o) = pl;
                    }
                }
            }
        }
        __syncthreads();   // publish this half's global stores block-wide
    }

    // ---- phase C: [q|r] = h_tile @ W2 (rows L2-hot from phases A/B) ----
    #pragma unroll
    for (int i = 0; i < 2; i++)
        #pragma unroll
        for (int jj = 0; jj < 8; jj++)
            #pragma unroll
            for (int kk = 0; kk < 4; kk++) acc[i][jj][kk] = 0.f;

    {
        const uint32_t* aH = (const uint32_t*)g_hh;
        const uint32_t* aL = (const uint32_t*)g_hl;
        const uint32_t* bH = (const uint32_t*)g_w2t_hi;
        const uint32_t* bL = (const uint32_t*)g_w2t_lo;

        GEMM_PHASE(aH, aL, bH, bL, grow, srow);
    }

    // epilogue: wc==0 -> q (no bias), wc==1 -> r (+b2)
    #pragma unroll
    for (int i = 0; i < 2; i++) {
        #pragma unroll
        for (int j = 0; j < 8; j++) {
            int r1 = row0 + wr * 32 + i * 16 + fr;
            int cc = j * 8 + fc * 2;
            #pragma unroll
            for (int hh = 0; hh < 2; hh++) {
                int rr = r1 + hh * 8;
                if (rr < NODES) {
                    float2 v;
                    v.x = acc[i][j][hh * 2 + 0];
                    v.y = acc[i][j][hh * 2 + 1];
                    if (wc == 0) {
                        *(float2*)&g_q[(size_t)rr * 64 + cc] = v;
                    } else {
                        v.x += sb2[cc];
                        v.y += sb2[cc + 1];
                        *(float2*)&g_r[(size_t)rr * 64 + cc] = v;
                    }
                }
            }
        }
    }
}

// ============================ layer-2 aggregation + z + fused decoder ============================
__global__ void __launch_bounds__(256) k_agg2(const float* __restrict__ Wd,
                                              const float* __restrict__ bd,
                                              float* __restrict__ z_out,
                                              float* __restrict__ xh_out) {
    __shared__ float4 sWd[64 * 32];
    __shared__ float  sZ[8][64];
    for (int i = threadIdx.x; i < 64 * 32; i += blockDim.x)
        sWd[i] = ((const float4*)Wd)[i];
    __syncthreads();

    const int wid = threadIdx.x >> 5;
    const int lane = threadIdx.x & 31;
    const int node = blockIdx.x * 8 + wid;
    if (node < NODES) {
        const int s0 = g_off[node], s1 = g_off[node + 1];
        float2 acc = make_float2(0.f, 0.f);
        int j = s0;
        for (; j + 3 < s1; j += 4) {
            int sa = g_srcs[j], sb = g_srcs[j + 1], sc = g_srcs[j + 2], sd = g_srcs[j + 3];
            float2 va = ((const float2*)(g_q + (size_t)sa * 64))[lane];
            float2 vb = ((const float2*)(g_q + (size_t)sb * 64))[lane];
            float2 vc = ((const float2*)(g_q + (size_t)sc * 64))[lane];
            float2 vd = ((const float2*)(g_q + (size_t)sd * 64))[lane];
            acc.x += (va.x + vb.x) + (vc.x + vd.x);
            acc.y += (va.y + vb.y) + (vc.y + vd.y);
        }
        for (; j < s1; j++) {
            int sa = g_srcs[j];
            float2 va = ((const float2*)(g_q + (size_t)sa * 64))[lane];
            acc.x += va.x; acc.y += va.y;
        }
        int deg = s1 - s0;
        float inv = 1.0f / (float)(deg > 0 ? deg : 1);
        float2 r2 = ((const float2*)(g_r + (size_t)node * 64))[lane];
        float2 zv;
        zv.x = acc.x * inv + r2.x;
        zv.y = acc.y * inv + r2.y;
        ((float2*)(z_out + (size_t)node * 64))[lane] = zv;
        sZ[wid][lane * 2]     = zv.x;
        sZ[wid][lane * 2 + 1] = zv.y;
        __syncwarp();
        float4 o = ((const float4*)bd)[lane];
        #pragma unroll 8
        for (int k = 0; k < 64; k++) {
            float zk = sZ[wid][k];
            float4 wv = sWd[k * 32 + lane];
            o.x = fmaf(zk, wv.x, o.x);
            o.y = fmaf(zk, wv.y, o.y);
            o.z = fmaf(zk, wv.z, o.z);
            o.w = fmaf(zk, wv.w, o.w);
        }
        ((float4*)(xh_out + (size_t)node * 128))[lane] = o;
    }
}

// ============================ launcher ============================
extern "C" void kernel_launch(void* const* d_in, const int* in_sizes, int n_in,
                              void* d_out, int out_size) {
    const float* x   = (const float*)d_in[0];
    const void*  ei  = d_in[1];
    const float* W1l = (const float*)d_in[2];
    const float* b1  = (const float*)d_in[3];
    const float* W1r = (const float*)d_in[4];
    const float* W2l = (const float*)d_in[5];
    const float* b2  = (const float*)d_in[6];
    const float* W2r = (const float*)d_in[7];
    const float* Wd  = (const float*)d_in[8];
    const float* bd  = (const float*)d_in[9];

    float* z_out  = (float*)d_out;                       // [N,64]
    float* xh_out = (float*)d_out + (size_t)NODES * 64;  // [N,128]

    cudaFuncSetAttribute(k_gemm, cudaFuncAttributeMaxDynamicSharedMemorySize, GEMM_SMEM);

    const int MT = (NODES + 127) / 128;   // 391 row tiles

    k_count<<<(EDGES + 255) / 256, 256>>>(ei, x);
    k_scan1<<<NB, 256>>>(W1l, W1r, W2l, W2r);
    k_scan23<<<NB, 256>>>();
    k_scatter<<<(EDGES + 255) / 256, 256>>>(ei);
    k_agg1<<<(NODES + 7) / 8, 256>>>();
    k_gemm<<<MT, 256, GEMM_SMEM>>>(b1, b2);
    k_agg2<<<(NODES + 7) / 8, 256>>>(Wd, bd, z_out, xh_out);
}